// round 9
// baseline (speedup 1.0000x reference)
#include <cuda_runtime.h>
#include <cuda_bf16.h>

// DenseIouPred: 72x72 IoU map around ind[0], window radius r.
// Scatter inverts to per-pixel gather (valid offsets <-> in-range pixels 1:1,
// gather index == own flat index).
// R9 (final): best-measured config (81 CTAs x 64 threads, scalar branchless
// body, kernel 4.22us = floor). 81*64 == 5184 exactly -> bounds check deleted
// (one pixel per thread, no tail). Vectorized variants (f2/f4) measured
// slower; block sizes 32/128/256 measured slower or equal.

#define W 72
#define H 72
#define NPIX (W * H)   // 5184 == 81 * 64

__device__ int g_default_radius = 10;

__global__ void dense_iou_kernel(const float* __restrict__ out0,   // (4, W, H)
                                 const int*   __restrict__ ind,
                                 const float* __restrict__ tgt,    // 4 floats
                                 const int*   __restrict__ radius_p,
                                 float*       __restrict__ dst)    // (W, H)
{
    const int i = blockIdx.x * 64 + threadIdx.x;   // exact grid: no bounds check

    // All loads issued unconditionally, mutually independent (MLP ~ 7).
    const int   ind0 = __ldg(ind);
    const int   r    = __ldg(radius_p);
    const float tl   = __ldg(tgt + 0);
    const float tr   = __ldg(tgt + 1);
    const float tt   = __ldg(tgt + 2);
    const float tb   = __ldg(tgt + 3);
    const float pl   = __ldg(out0 + 0 * NPIX + i);
    const float pr   = __ldg(out0 + 1 * NPIX + i);
    const float pt   = __ldg(out0 + 2 * NPIX + i);
    const float pb   = __ldg(out0 + 3 * NPIX + i);

    const int row = i / W;
    const int col = i - row * W;
    const int cw  = ind0 % W;
    const int ch  = ind0 / W;

    const int rw = col - cw;
    const int rh = row - ch;

    const float frw = (float)rw;
    const float frh = (float)rh;
    const float twl = tl + frw;
    const float twr = tr - frw;
    const float tht = tt + frh;
    const float thb = tb - frh;

    // Branchless validity
    const bool valid =
        (rw >= -r) & (rw <= r) & (rh >= -r) & (rh <= r) &
        (twl >= 0.0f) & (twr >= 0.0f) & (tht >= 0.0f) & (thb >= 0.0f);

    const float target_area = (twl + twr) * (tht + thb);
    const float pred_area   = (pl + pr) * (pt + pb);
    const float w_int = fminf(pl, twl) + fminf(pr, twr);
    const float h_int = fminf(pb, thb) + fminf(pt, tht);
    const float area_int   = w_int * h_int;
    const float area_union = target_area + pred_area - area_int;
    const float iou = __fdividef(area_int + 1.0f, area_union + 1.0f);

    dst[i] = valid ? iou : 0.0f;
}

extern "C" void kernel_launch(void* const* d_in, const int* in_sizes, int n_in,
                              void* d_out, int out_size)
{
    const float* output = (const float*)d_in[0];   // (128, 8, 4, 72, 72)
    const int*   ind    = (const int*)  d_in[1];   // (128, 8, 1)
    const float* target = (const float*)d_in[2];   // (128, 8, 4)
    float*       dst    = (float*)d_out;           // (72, 72)

    const int* radius = nullptr;
    if (n_in >= 4) {
        radius = (const int*)d_in[3];
    } else {
        void* p = nullptr;
        cudaGetSymbolAddress(&p, g_default_radius);  // capture-safe, no alloc
        radius = (const int*)p;
    }

    dense_iou_kernel<<<NPIX / 64, 64>>>(output, ind, target, radius, dst);
}

// round 11
// speedup vs baseline: 1.1615x; 1.1615x over previous
#include <cuda_runtime.h>
#include <cuda_bf16.h>

// DenseIouPred: 72x72 IoU map around ind[0], window radius r.
// Scatter inverts to per-pixel gather (valid offsets <-> in-range pixels 1:1,
// gather index == own flat index).
// R9 (final): best-measured config (81 CTAs x 64 threads, scalar branchless
// body, kernel 4.22us = floor). 81*64 == 5184 exactly -> bounds check deleted
// (one pixel per thread, no tail). Vectorized variants (f2/f4) measured
// slower; block sizes 32/128/256 measured slower or equal.

#define W 72
#define H 72
#define NPIX (W * H)   // 5184 == 81 * 64

__device__ int g_default_radius = 10;

__global__ void dense_iou_kernel(const float* __restrict__ out0,   // (4, W, H)
                                 const int*   __restrict__ ind,
                                 const float* __restrict__ tgt,    // 4 floats
                                 const int*   __restrict__ radius_p,
                                 float*       __restrict__ dst)    // (W, H)
{
    const int i = blockIdx.x * 64 + threadIdx.x;   // exact grid: no bounds check

    // All loads issued unconditionally, mutually independent (MLP ~ 7).
    const int   ind0 = __ldg(ind);
    const int   r    = __ldg(radius_p);
    const float tl   = __ldg(tgt + 0);
    const float tr   = __ldg(tgt + 1);
    const float tt   = __ldg(tgt + 2);
    const float tb   = __ldg(tgt + 3);
    const float pl   = __ldg(out0 + 0 * NPIX + i);
    const float pr   = __ldg(out0 + 1 * NPIX + i);
    const float pt   = __ldg(out0 + 2 * NPIX + i);
    const float pb   = __ldg(out0 + 3 * NPIX + i);

    const int row = i / W;
    const int col = i - row * W;
    const int cw  = ind0 % W;
    const int ch  = ind0 / W;

    const int rw = col - cw;
    const int rh = row - ch;

    const float frw = (float)rw;
    const float frh = (float)rh;
    const float twl = tl + frw;
    const float twr = tr - frw;
    const float tht = tt + frh;
    const float thb = tb - frh;

    // Branchless validity
    const bool valid =
        (rw >= -r) & (rw <= r) & (rh >= -r) & (rh <= r) &
        (twl >= 0.0f) & (twr >= 0.0f) & (tht >= 0.0f) & (thb >= 0.0f);

    const float target_area = (twl + twr) * (tht + thb);
    const float pred_area   = (pl + pr) * (pt + pb);
    const float w_int = fminf(pl, twl) + fminf(pr, twr);
    const float h_int = fminf(pb, thb) + fminf(pt, tht);
    const float area_int   = w_int * h_int;
    const float area_union = target_area + pred_area - area_int;
    const float iou = __fdividef(area_int + 1.0f, area_union + 1.0f);

    dst[i] = valid ? iou : 0.0f;
}

extern "C" void kernel_launch(void* const* d_in, const int* in_sizes, int n_in,
                              void* d_out, int out_size)
{
    const float* output = (const float*)d_in[0];   // (128, 8, 4, 72, 72)
    const int*   ind    = (const int*)  d_in[1];   // (128, 8, 1)
    const float* target = (const float*)d_in[2];   // (128, 8, 4)
    float*       dst    = (float*)d_out;           // (72, 72)

    const int* radius = nullptr;
    if (n_in >= 4) {
        radius = (const int*)d_in[3];
    } else {
        void* p = nullptr;
        cudaGetSymbolAddress(&p, g_default_radius);  // capture-safe, no alloc
        radius = (const int*)p;
    }

    dense_iou_kernel<<<NPIX / 64, 64>>>(output, ind, target, radius, dst);
}

// round 12
// speedup vs baseline: 1.1688x; 1.0063x over previous
#include <cuda_runtime.h>
#include <cuda_bf16.h>

// DenseIouPred: 72x72 IoU map around ind[0], window radius r.
// Scatter inverts to per-pixel gather (valid offsets <-> in-range pixels 1:1,
// gather index == own flat index).
// R12 (convergence): measured-best config (81 CTAs x 64 threads, scalar
// branchless body, exact grid, kernel floor 4.22us across R6/R11). Single
// remaining micro-lever: __stwt streaming store (skip L2 allocation on the
// write-out; output is never re-read in-kernel). All other variants measured
// slower: f2/f4 vectorization, 32/128/256-thread blocks, branchy loads.

#define W 72
#define H 72
#define NPIX (W * H)   // 5184 == 81 * 64

__device__ int g_default_radius = 10;

__global__ void dense_iou_kernel(const float* __restrict__ out0,   // (4, W, H)
                                 const int*   __restrict__ ind,
                                 const float* __restrict__ tgt,    // 4 floats
                                 const int*   __restrict__ radius_p,
                                 float*       __restrict__ dst)    // (W, H)
{
    const int i = blockIdx.x * 64 + threadIdx.x;   // exact grid: no bounds check

    // All loads issued unconditionally, mutually independent (MLP ~ 7).
    const int   ind0 = __ldg(ind);
    const int   r    = __ldg(radius_p);
    const float tl   = __ldg(tgt + 0);
    const float tr   = __ldg(tgt + 1);
    const float tt   = __ldg(tgt + 2);
    const float tb   = __ldg(tgt + 3);
    const float pl   = __ldg(out0 + 0 * NPIX + i);
    const float pr   = __ldg(out0 + 1 * NPIX + i);
    const float pt   = __ldg(out0 + 2 * NPIX + i);
    const float pb   = __ldg(out0 + 3 * NPIX + i);

    const int row = i / W;
    const int col = i - row * W;
    const int cw  = ind0 % W;
    const int ch  = ind0 / W;

    const int rw = col - cw;
    const int rh = row - ch;

    const float frw = (float)rw;
    const float frh = (float)rh;
    const float twl = tl + frw;
    const float twr = tr - frw;
    const float tht = tt + frh;
    const float thb = tb - frh;

    // Branchless validity
    const bool valid =
        (rw >= -r) & (rw <= r) & (rh >= -r) & (rh <= r) &
        (twl >= 0.0f) & (twr >= 0.0f) & (tht >= 0.0f) & (thb >= 0.0f);

    const float target_area = (twl + twr) * (tht + thb);
    const float pred_area   = (pl + pr) * (pt + pb);
    const float w_int = fminf(pl, twl) + fminf(pr, twr);
    const float h_int = fminf(pb, thb) + fminf(pt, tht);
    const float area_int   = w_int * h_int;
    const float area_union = target_area + pred_area - area_int;
    const float iou = __fdividef(area_int + 1.0f, area_union + 1.0f);

    // Streaming store: output is write-once, never re-read in-kernel.
    __stwt(dst + i, valid ? iou : 0.0f);
}

extern "C" void kernel_launch(void* const* d_in, const int* in_sizes, int n_in,
                              void* d_out, int out_size)
{
    const float* output = (const float*)d_in[0];   // (128, 8, 4, 72, 72)
    const int*   ind    = (const int*)  d_in[1];   // (128, 8, 1)
    const float* target = (const float*)d_in[2];   // (128, 8, 4)
    float*       dst    = (float*)d_out;           // (72, 72)

    const int* radius = nullptr;
    if (n_in >= 4) {
        radius = (const int*)d_in[3];
    } else {
        void* p = nullptr;
        cudaGetSymbolAddress(&p, g_default_radius);  // capture-safe, no alloc
        radius = (const int*)p;
    }

    dense_iou_kernel<<<NPIX / 64, 64>>>(output, ind, target, radius, dst);
}

// round 14
// speedup vs baseline: 1.1835x; 1.0127x over previous
#include <cuda_runtime.h>
#include <cuda_bf16.h>

// DenseIouPred: 72x72 IoU map around ind[0], window radius r.
// Scatter inverts to per-pixel gather (valid offsets <-> in-range pixels 1:1,
// gather index == own flat index).
// R14 (FINAL, = R12/R13 unchanged; R13 died to broker infra, no measurement).
// Converged configuration:
//   - 81 CTAs x 64 threads (exact grid, no bounds check) — kernel floor
//     4.22-4.26us, reproduced R6/R11/R12.
//   - All loads hoisted & independent (MLP~7), branchless validity,
//     __fdividef, __stwt streaming store.
//   - Measured-slower: 256t/128t/32t blocks, float2/float4 bodies, branchy
//     loads. Kernel is launch-overhead bound (all pipes <0.4% in ncu);
//     remaining harness variance is replay noise (~±0.5us), not work.

#define W 72
#define H 72
#define NPIX (W * H)   // 5184 == 81 * 64

__device__ int g_default_radius = 10;

__global__ void dense_iou_kernel(const float* __restrict__ out0,   // (4, W, H)
                                 const int*   __restrict__ ind,
                                 const float* __restrict__ tgt,    // 4 floats
                                 const int*   __restrict__ radius_p,
                                 float*       __restrict__ dst)    // (W, H)
{
    const int i = blockIdx.x * 64 + threadIdx.x;   // exact grid: no bounds check

    // All loads issued unconditionally, mutually independent (MLP ~ 7).
    const int   ind0 = __ldg(ind);
    const int   r    = __ldg(radius_p);
    const float tl   = __ldg(tgt + 0);
    const float tr   = __ldg(tgt + 1);
    const float tt   = __ldg(tgt + 2);
    const float tb   = __ldg(tgt + 3);
    const float pl   = __ldg(out0 + 0 * NPIX + i);
    const float pr   = __ldg(out0 + 1 * NPIX + i);
    const float pt   = __ldg(out0 + 2 * NPIX + i);
    const float pb   = __ldg(out0 + 3 * NPIX + i);

    const int row = i / W;
    const int col = i - row * W;
    const int cw  = ind0 % W;
    const int ch  = ind0 / W;

    const int rw = col - cw;
    const int rh = row - ch;

    const float frw = (float)rw;
    const float frh = (float)rh;
    const float twl = tl + frw;
    const float twr = tr - frw;
    const float tht = tt + frh;
    const float thb = tb - frh;

    // Branchless validity
    const bool valid =
        (rw >= -r) & (rw <= r) & (rh >= -r) & (rh <= r) &
        (twl >= 0.0f) & (twr >= 0.0f) & (tht >= 0.0f) & (thb >= 0.0f);

    const float target_area = (twl + twr) * (tht + thb);
    const float pred_area   = (pl + pr) * (pt + pb);
    const float w_int = fminf(pl, twl) + fminf(pr, twr);
    const float h_int = fminf(pb, thb) + fminf(pt, tht);
    const float area_int   = w_int * h_int;
    const float area_union = target_area + pred_area - area_int;
    const float iou = __fdividef(area_int + 1.0f, area_union + 1.0f);

    // Streaming store: output is write-once, never re-read in-kernel.
    __stwt(dst + i, valid ? iou : 0.0f);
}

extern "C" void kernel_launch(void* const* d_in, const int* in_sizes, int n_in,
                              void* d_out, int out_size)
{
    const float* output = (const float*)d_in[0];   // (128, 8, 4, 72, 72)
    const int*   ind    = (const int*)  d_in[1];   // (128, 8, 1)
    const float* target = (const float*)d_in[2];   // (128, 8, 4)
    float*       dst    = (float*)d_out;           // (72, 72)

    const int* radius = nullptr;
    if (n_in >= 4) {
        radius = (const int*)d_in[3];
    } else {
        void* p = nullptr;
        cudaGetSymbolAddress(&p, g_default_radius);  // capture-safe, no alloc
        radius = (const int*)p;
    }

    dense_iou_kernel<<<NPIX / 64, 64>>>(output, ind, target, radius, dst);
}